// round 2
// baseline (speedup 1.0000x reference)
#include <cuda_runtime.h>
#include <stdint.h>
#include <float.h>

#define NROWS  65536
#define DIMS   256
#define NCODES 1024
#define TM     64          // rows per block
#define TC     64          // codes per chunk
#define RSTR   260         // padded row stride (floats), 260%32=4 -> conflict-free frags
#define MARGIN 0.01f       // rescore margin (>= ~35x worst-case tf32 dot error)

// smem layout (bytes):
//   zs   [TM][RSTR] f32 : 66560   (row-major, fp32 master copy)
//   es   [TC][RSTR] f32 : 66560
//   z2s  [TM]  f32      : 256
//   e2s  [TC]  f32      : 256
//   aminI[TM]  int      : 256
//   bestP[TM]  u64      : 512
//   idxs [TM]  int      : 256
//   red  [256] double   : 2048
#define SMEM_BYTES (66560*2 + 256 + 256 + 256 + 512 + 256 + 2048)

__device__ float  g_e2[NCODES];
__device__ double g_loss_accum;

// ---------------------------------------------------------------------------
__device__ __forceinline__ unsigned f2tf(float f) {
    unsigned u; asm("cvt.rna.tf32.f32 %0, %1;" : "=r"(u) : "f"(f)); return u;
}
__device__ __forceinline__ void mma8(float* c, unsigned a0, unsigned a1,
                                     unsigned a2, unsigned a3,
                                     unsigned b0, unsigned b1) {
    asm("mma.sync.aligned.m16n8k8.row.col.f32.tf32.tf32.f32 "
        "{%0,%1,%2,%3},{%4,%5,%6,%7},{%8,%9},{%0,%1,%2,%3};"
        : "+f"(c[0]), "+f"(c[1]), "+f"(c[2]), "+f"(c[3])
        : "r"(a0), "r"(a1), "r"(a2), "r"(a3), "r"(b0), "r"(b1));
}

// ---------------------------------------------------------------------------
// Kernel A: per-code squared norms + zero the loss accumulator (every replay)
// ---------------------------------------------------------------------------
__global__ void vq_prep(const float* __restrict__ emb) {
    if (blockIdx.x == 0 && threadIdx.x == 0) g_loss_accum = 0.0;
    int warp = (blockIdx.x * blockDim.x + threadIdx.x) >> 5;
    int lane = threadIdx.x & 31;
    if (warp < NCODES) {
        const float* row = emb + warp * DIMS;
        float s = 0.f;
#pragma unroll
        for (int i = 0; i < DIMS / 32; i++) {
            float v = row[lane + 32 * i];
            s = __fadd_rn(s, __fmul_rn(v, v));
        }
#pragma unroll
        for (int o = 16; o > 0; o >>= 1)
            s = __fadd_rn(s, __shfl_down_sync(0xffffffffu, s, o));
        if (lane == 0) g_e2[warp] = s;
    }
}

// ---------------------------------------------------------------------------
// Chunk worker: tf32 MMA over 16 rows x 32 codes x 256 k per warp.
// RESCORE=false: track approx per-thread row mins.
// RESCORE=true : exact fp32 rescore of codes within MARGIN of approx min.
// ---------------------------------------------------------------------------
template <bool RESCORE>
__device__ __forceinline__ void process_chunk(
    const float* __restrict__ zs, const float* __restrict__ es,
    const float* __restrict__ z2s, const float* __restrict__ e2s,
    int chunkBase, int rg, int cs, int lane,
    const int* __restrict__ aminI, unsigned long long* bestP,
    float& amin0, float& amin1)
{
    const int qr = lane >> 2;      // 0..7
    const int qc = lane & 3;       // 0..3
    const int r0 = rg * 16 + qr;
    const float* za = zs + r0 * RSTR;

    float acc[4][4];
#pragma unroll
    for (int nt = 0; nt < 4; nt++)
#pragma unroll
        for (int e = 0; e < 4; e++) acc[nt][e] = 0.f;

#pragma unroll 4
    for (int kt = 0; kt < DIMS / 8; kt++) {
        int kk = kt * 8 + qc;
        unsigned a0 = f2tf(za[kk]);
        unsigned a1 = f2tf(za[8 * RSTR + kk]);
        unsigned a2 = f2tf(za[kk + 4]);
        unsigned a3 = f2tf(za[8 * RSTR + kk + 4]);
#pragma unroll
        for (int nt = 0; nt < 4; nt++) {
            int c = cs * 32 + nt * 8 + qr;
            unsigned b0 = f2tf(es[c * RSTR + kk]);
            unsigned b1 = f2tf(es[c * RSTR + kk + 4]);
            mma8(acc[nt], a0, a1, a2, a3, b0, b1);
        }
    }

#pragma unroll
    for (int nt = 0; nt < 4; nt++) {
        int cb = cs * 32 + nt * 8 + 2 * qc;
#pragma unroll
        for (int e = 0; e < 4; e++) {
            int row = r0 + ((e >= 2) ? 8 : 0);
            int cl  = cb + (e & 1);                 // local code in chunk
            float da = z2s[row] + e2s[cl] - 2.0f * acc[nt][e];
            if (!RESCORE) {
                if (e >= 2) amin1 = fminf(amin1, da);
                else        amin0 = fminf(amin0, da);
            } else {
                float thr = __int_as_float(aminI[row]) + MARGIN;
                if (da <= thr) {
                    int code = chunkBase + cl;
                    const float* zr = zs + row * RSTR;
                    const float* er = es + cl * RSTR;
                    float d0 = 0.f, d1 = 0.f, d2 = 0.f, d3 = 0.f;
                    for (int k = 0; k < DIMS; k += 4) {
                        d0 = fmaf(zr[k + 0], er[k + 0], d0);
                        d1 = fmaf(zr[k + 1], er[k + 1], d1);
                        d2 = fmaf(zr[k + 2], er[k + 2], d2);
                        d3 = fmaf(zr[k + 3], er[k + 3], d3);
                    }
                    float dot  = __fadd_rn(__fadd_rn(d0, d1), __fadd_rn(d2, d3));
                    float t    = __fadd_rn(z2s[row], g_e2[code]);
                    float dist = __fsub_rn(t, __fmul_rn(2.0f, dot));
                    unsigned long long p =
                        ((unsigned long long)__float_as_uint(dist) << 32) |
                        (unsigned long long)(unsigned)code;
                    atomicMin(&bestP[row], p);
                }
            }
        }
    }
}

// ---------------------------------------------------------------------------
// Main kernel
// ---------------------------------------------------------------------------
__global__ void __launch_bounds__(256, 1)
vq_main(const float* __restrict__ z, const float* __restrict__ emb,
        float* __restrict__ out) {
    extern __shared__ char smraw[];
    float* zs  = (float*)smraw;                 // [TM][RSTR]
    float* es  = zs + TM * RSTR;                // [TC][RSTR]
    float* z2s = es + TC * RSTR;                // [TM]
    float* e2s = z2s + TM;                      // [TC]
    int*   aminI = (int*)(e2s + TC);            // [TM]
    unsigned long long* bestP = (unsigned long long*)(aminI + TM);  // [TM]
    int*    idxs = (int*)(bestP + TM);          // [TM]
    double* red  = (double*)(idxs + TM);        // [256]

    const int tid  = threadIdx.x;
    const int warp = tid >> 5;
    const int lane = tid & 31;
    const int rg   = warp >> 1;      // row group (16 rows)
    const int cs   = warp & 1;       // 32-code sub-group within chunk
    const int rowBase = blockIdx.x * TM;
    const float* zblk = z + (size_t)rowBase * DIMS;

    // ---- stage z tile (row-major fp32) ----
    for (int i = tid; i < TM * (DIMS / 4); i += 256) {
        int r  = i >> 6;
        int k4 = i & 63;
        float4 v = ((const float4*)zblk)[(size_t)r * (DIMS / 4) + k4];
        *(float4*)&zs[r * RSTR + 4 * k4] = v;
    }
    __syncthreads();

    if (tid < TM) {
        // per-row ||z||^2, same rounding/order as round 1
        float s = 0.f;
        const float* zr = zs + tid * RSTR;
        for (int k = 0; k < DIMS; k++)
            s = __fadd_rn(s, __fmul_rn(zr[k], zr[k]));
        z2s[tid]  = s;
        aminI[tid] = __float_as_int(FLT_MAX);
        bestP[tid] = ~0ull;
    }

    float amin0 = FLT_MAX, amin1 = FLT_MAX;

    // ---- pass A: approx distances, per-row approx min ----
    for (int chunk = 0; chunk < NCODES / TC; chunk++) {
        __syncthreads();
        const float* eblk = emb + (size_t)chunk * TC * DIMS;
        for (int i = tid; i < TC * (DIMS / 4); i += 256) {
            int c  = i >> 6;
            int k4 = i & 63;
            float4 v = ((const float4*)eblk)[(size_t)c * (DIMS / 4) + k4];
            *(float4*)&es[c * RSTR + 4 * k4] = v;
        }
        if (tid < TC) e2s[tid] = g_e2[chunk * TC + tid];
        __syncthreads();
        process_chunk<false>(zs, es, z2s, e2s, chunk * TC, rg, cs, lane,
                             aminI, bestP, amin0, amin1);
    }

    {
        int r0 = rg * 16 + (lane >> 2);
        atomicMin(&aminI[r0],     __float_as_int(amin0));
        atomicMin(&aminI[r0 + 8], __float_as_int(amin1));
    }
    __syncthreads();

    // ---- pass B: recompute approx, exact-rescore candidates ----
    for (int chunk = 0; chunk < NCODES / TC; chunk++) {
        __syncthreads();
        const float* eblk = emb + (size_t)chunk * TC * DIMS;
        for (int i = tid; i < TC * (DIMS / 4); i += 256) {
            int c  = i >> 6;
            int k4 = i & 63;
            float4 v = ((const float4*)eblk)[(size_t)c * (DIMS / 4) + k4];
            *(float4*)&es[c * RSTR + 4 * k4] = v;
        }
        if (tid < TC) e2s[tid] = g_e2[chunk * TC + tid];
        __syncthreads();
        process_chunk<true>(zs, es, z2s, e2s, chunk * TC, rg, cs, lane,
                            aminI, bestP, amin0, amin1);
    }

    __syncthreads();
    if (tid < TM) idxs[tid] = (int)(bestP[tid] & 0xffffffffull);
    __syncthreads();

    // ---- epilogue: gather, STE output, loss partial sum ----
    double lsum = 0.0;
    float* outblk = out + (size_t)rowBase * DIMS;
    for (int t = 0; t < TM * DIMS / 256; t++) {
        int e = tid + t * 256;
        int r = e >> 8;            // DIMS == 256
        int d = e & 255;
        float q  = emb[(size_t)idxs[r] * DIMS + d];
        float zv = zs[r * RSTR + d];
        float diff = __fsub_rn(q, zv);
        outblk[e]  = __fadd_rn(zv, diff);   // z + stopgrad(q - z)
        lsum += (double)__fmul_rn(diff, diff);
    }
    red[tid] = lsum;
    __syncthreads();
    for (int s = 128; s > 0; s >>= 1) {
        if (tid < s) red[tid] += red[tid + s];
        __syncthreads();
    }
    if (tid == 0) atomicAdd(&g_loss_accum, red[0]);
}

// ---------------------------------------------------------------------------
__global__ void vq_finalize(float* __restrict__ out, int out_size) {
    double mean = g_loss_accum / (double)((size_t)NROWS * DIMS);
    float loss = (float)(0.5 * mean);
    out[out_size - 2] = loss;   // commitment_loss
    out[out_size - 1] = loss;   // emb_loss
}

// ---------------------------------------------------------------------------
extern "C" void kernel_launch(void* const* d_in, const int* in_sizes, int n_in,
                              void* d_out, int out_size) {
    const float* z   = (const float*)d_in[0];
    const float* emb = (const float*)d_in[1];
    if (n_in >= 2 && in_sizes[0] == NCODES * DIMS && in_sizes[1] == NROWS * DIMS) {
        emb = (const float*)d_in[0];
        z   = (const float*)d_in[1];
    }
    float* out = (float*)d_out;

    vq_prep<<<(NCODES * 32 + 255) / 256, 256>>>(emb);

    cudaFuncSetAttribute(vq_main, cudaFuncAttributeMaxDynamicSharedMemorySize,
                         SMEM_BYTES);
    vq_main<<<NROWS / TM, 256, SMEM_BYTES>>>(z, emb, out);

    vq_finalize<<<1, 1>>>(out, out_size);
}

// round 3
// speedup vs baseline: 1.2392x; 1.2392x over previous
#include <cuda_runtime.h>
#include <stdint.h>
#include <float.h>

#define NROWS   65536
#define DIMS    256
#define NCODES  1024
#define TM      128        // rows per block
#define TC      64         // codes per chunk
#define NCHUNK  (NCODES / TC)
#define MARGIN  4e-4f      // >= ~6x probabilistic tf32 error bound + rounding slack
#define RSTR2   260        // pass-B plain e-tile row stride (floats)

// ---- smem layout (bytes) -------------------------------------------------
#define OFF_ZSF   0                         // tf32 frag-layout z   [32768 f] 131072
#define OFF_EREG  131072                    // esf [16384 f] / es2 [64*260 f] 66560
#define OFF_T2A   (OFF_EREG + 66560)        // u64 [128*8]                      8192
#define OFF_BEST1 (OFF_T2A + 8192)          // u64 [128]                        1024
#define OFF_BESTB (OFF_BEST1 + 1024)        // u64 [128]                        1024
#define OFF_RED   (OFF_BESTB + 1024)        // double [256]                     2048
#define OFF_T2B   (OFF_RED + 2048)          // f32 [128*8]                      4096
#define OFF_Z2    (OFF_T2B + 4096)          // f32 [128]                         512
#define OFF_E2    (OFF_Z2 + 512)            // f32 [64]                          256
#define OFF_PBUF  (OFF_E2 + 256)            // f32 [64*4]                       1024
#define OFF_IDX   (OFF_PBUF + 1024)         // i32 [128]                         512
#define OFF_FROWS (OFF_IDX + 512)           // i32 [128]                         512
#define OFF_NFLAG (OFF_FROWS + 512)         // i32 [1]                             4
#define SMEM_BYTES (OFF_NFLAG + 4)

__device__ float  g_e2[NCODES];
__device__ double g_loss_accum;

__device__ __forceinline__ unsigned f2tf(float f) {
    unsigned u; asm("cvt.rna.tf32.f32 %0, %1;" : "=r"(u) : "f"(f)); return u;
}
__device__ __forceinline__ void mma8(float* c, unsigned a0, unsigned a1,
                                     unsigned a2, unsigned a3,
                                     unsigned b0, unsigned b1) {
    asm("mma.sync.aligned.m16n8k8.row.col.f32.tf32.tf32.f32 "
        "{%0,%1,%2,%3},{%4,%5,%6,%7},{%8,%9},{%0,%1,%2,%3};"
        : "+f"(c[0]), "+f"(c[1]), "+f"(c[2]), "+f"(c[3])
        : "r"(a0), "r"(a1), "r"(a2), "r"(a3), "r"(b0), "r"(b1));
}
#define FU(x) __float_as_uint(x)

// ---------------------------------------------------------------------------
__global__ void vq_prep(const float* __restrict__ emb) {
    if (blockIdx.x == 0 && threadIdx.x == 0) g_loss_accum = 0.0;
    int warp = (blockIdx.x * blockDim.x + threadIdx.x) >> 5;
    int lane = threadIdx.x & 31;
    if (warp < NCODES) {
        const float* row = emb + warp * DIMS;
        float s = 0.f;
#pragma unroll
        for (int i = 0; i < DIMS / 32; i++) {
            float v = row[lane + 32 * i];
            s = __fadd_rn(s, __fmul_rn(v, v));
        }
#pragma unroll
        for (int o = 16; o > 0; o >>= 1)
            s = __fadd_rn(s, __shfl_down_sync(0xffffffffu, s, o));
        if (lane == 0) g_e2[warp] = s;
    }
}

// ---------------------------------------------------------------------------
__global__ void __launch_bounds__(256, 1)
vq_main(const float* __restrict__ z, const float* __restrict__ emb,
        float* __restrict__ out) {
    extern __shared__ char sm[];
    float*  zsf   = (float*)(sm + OFF_ZSF);
    float*  esf   = (float*)(sm + OFF_EREG);   // pass A (tf32 frag layout)
    float*  es2   = (float*)(sm + OFF_EREG);   // pass B (plain fp32 rows)
    unsigned long long* t2a   = (unsigned long long*)(sm + OFF_T2A);
    unsigned long long* best1 = (unsigned long long*)(sm + OFF_BEST1);
    unsigned long long* bestB = (unsigned long long*)(sm + OFF_BESTB);
    double* red   = (double*)(sm + OFF_RED);
    float*  t2b   = (float*)(sm + OFF_T2B);
    float*  z2s   = (float*)(sm + OFF_Z2);
    float*  e2s   = (float*)(sm + OFF_E2);
    float*  pbuf  = (float*)(sm + OFF_PBUF);
    int*    idxs  = (int*)(sm + OFF_IDX);
    int*    frows = (int*)(sm + OFF_FROWS);
    int*    nflagp= (int*)(sm + OFF_NFLAG);

    const int tid  = threadIdx.x;
    const int lane = tid & 31;
    const int warp = tid >> 5;
    const int wr   = warp >> 1;          // row group: rows wr*32 .. +31
    const int wc   = warp & 1;           // code group: codes wc*32 .. +31
    const int qr   = lane >> 2;
    const int qc   = lane & 3;
    const int rowBase = blockIdx.x * TM;
    const float* zblk = z + (size_t)rowBase * DIMS;

    if (tid == 0) nflagp[0] = 0;

    // ---- stage z tile into tf32 fragment layout ----
    for (int i = tid; i < TM * (DIMS / 4); i += 256) {
        int r  = i >> 6;
        int k4 = i & 63;
        float4 v = ((const float4*)zblk)[(size_t)r * (DIMS / 4) + k4];
        int rg = r >> 5, rr = r & 31, m = rr >> 4;
        int hi = (rr & 15) >> 3, q8 = rr & 7;
        float vv[4] = {v.x, v.y, v.z, v.w};
#pragma unroll
        for (int j = 0; j < 4; j++) {
            int k = 4 * k4 + j;
            int kt = k >> 3, kc = (k & 7) >> 2, qcc = k & 3;
            int ln = q8 * 4 + qcc;
            zsf[(((rg * 32 + kt) * 32 + ln) << 3) + m * 4 + hi + 2 * kc] =
                __uint_as_float(f2tf(vv[j]));
        }
    }
    // ---- per-row exact ||z||^2 (k-ascending, as in R1/R2) ----
    if (tid < TM) {
        const float4* zr = (const float4*)(zblk + (size_t)tid * DIMS);
        float s = 0.f;
        for (int k4 = 0; k4 < DIMS / 4; k4++) {
            float4 v = __ldg(&zr[k4]);
            s = __fadd_rn(s, __fmul_rn(v.x, v.x));
            s = __fadd_rn(s, __fmul_rn(v.y, v.y));
            s = __fadd_rn(s, __fmul_rn(v.z, v.z));
            s = __fadd_rn(s, __fmul_rn(v.w, v.w));
        }
        z2s[tid] = s;
    }

    unsigned long long b1[4];
    float b2[4];
#pragma unroll
    for (int i = 0; i < 4; i++) { b1[i] = ~0ull; b2[i] = FLT_MAX; }

    // ================= pass A: tf32 MMA + per-row approx top-2 ============
    for (int chunk = 0; chunk < NCHUNK; chunk++) {
        __syncthreads();
        const float* eblk = emb + (size_t)chunk * TC * DIMS;
        for (int i = tid; i < TC * (DIMS / 4); i += 256) {
            int c  = i >> 6;
            int k4 = i & 63;
            float4 v = ((const float4*)eblk)[(size_t)c * (DIMS / 4) + k4];
            int cg = c >> 5, cc = c & 31, n = cc >> 3, q8 = cc & 7;
            float vv[4] = {v.x, v.y, v.z, v.w};
#pragma unroll
            for (int j = 0; j < 4; j++) {
                int k = 4 * k4 + j;
                int kt = k >> 3, kc = (k & 7) >> 2, qcc = k & 3;
                int ln = q8 * 4 + qcc;
                esf[(((cg * 32 + kt) * 32 + ln) << 3) + n * 2 + kc] =
                    __uint_as_float(f2tf(vv[j]));
            }
        }
        if (tid < TC) e2s[tid] = g_e2[chunk * TC + tid];
        __syncthreads();

        float acc[2][4][4];
#pragma unroll
        for (int m = 0; m < 2; m++)
#pragma unroll
            for (int n = 0; n < 4; n++)
#pragma unroll
                for (int e = 0; e < 4; e++) acc[m][n][e] = 0.f;

        const float4* za = (const float4*)&zsf[((wr * 32) * 32 + lane) << 3];
        const float4* ea = (const float4*)&esf[((wc * 32) * 32 + lane) << 3];
#pragma unroll 4
        for (int kt = 0; kt < 32; kt++) {
            float4 A0 = za[kt * 64 + 0];
            float4 A1 = za[kt * 64 + 1];
            float4 B0 = ea[kt * 64 + 0];
            float4 B1 = ea[kt * 64 + 1];
            mma8(acc[0][0], FU(A0.x), FU(A0.y), FU(A0.z), FU(A0.w), FU(B0.x), FU(B0.y));
            mma8(acc[0][1], FU(A0.x), FU(A0.y), FU(A0.z), FU(A0.w), FU(B0.z), FU(B0.w));
            mma8(acc[0][2], FU(A0.x), FU(A0.y), FU(A0.z), FU(A0.w), FU(B1.x), FU(B1.y));
            mma8(acc[0][3], FU(A0.x), FU(A0.y), FU(A0.z), FU(A0.w), FU(B1.z), FU(B1.w));
            mma8(acc[1][0], FU(A1.x), FU(A1.y), FU(A1.z), FU(A1.w), FU(B0.x), FU(B0.y));
            mma8(acc[1][1], FU(A1.x), FU(A1.y), FU(A1.z), FU(A1.w), FU(B0.z), FU(B0.w));
            mma8(acc[1][2], FU(A1.x), FU(A1.y), FU(A1.z), FU(A1.w), FU(B1.x), FU(B1.y));
            mma8(acc[1][3], FU(A1.x), FU(A1.y), FU(A1.z), FU(A1.w), FU(B1.z), FU(B1.w));
        }

        // approx distances -> per-thread top-2 per row-slot
#pragma unroll
        for (int m = 0; m < 2; m++) {
#pragma unroll
            for (int e = 0; e < 4; e++) {
                int slot = m * 2 + (e >> 1);
                int row  = wr * 32 + m * 16 + qr + ((e >> 1) << 3);
                float z2 = z2s[row];
#pragma unroll
                for (int n = 0; n < 4; n++) {
                    int l    = wc * 32 + n * 8 + 2 * qc + (e & 1);
                    int code = chunk * TC + l;
                    float da = z2 + e2s[l] - 2.0f * acc[m][n][e];
                    unsigned long long p =
                        ((unsigned long long)FU(da) << 32) | (unsigned)code;
                    if (p < b1[slot]) {
                        b2[slot] = __uint_as_float((unsigned)(b1[slot] >> 32));
                        b1[slot] = p;
                    } else {
                        float v = da;
                        if (v < b2[slot]) b2[slot] = v;
                    }
                }
            }
        }
    }

    // ---- cross-thread top-2 merge (8 contributions per row) ----
    __syncthreads();
#pragma unroll
    for (int s = 0; s < 4; s++) {
        int row = wr * 32 + (s >> 1) * 16 + ((s & 1) << 3) + qr;
        t2a[row * 8 + wc * 4 + qc] = b1[s];
        t2b[row * 8 + wc * 4 + qc] = b2[s];
    }
    __syncthreads();
    if (tid < TM) {
        unsigned long long m1 = ~0ull;
        float sec = FLT_MAX;
#pragma unroll
        for (int i = 0; i < 8; i++) {
            unsigned long long p = t2a[tid * 8 + i];
            float v = __uint_as_float((unsigned)(p >> 32));
            if (p < m1) {
                float ov = __uint_as_float((unsigned)(m1 >> 32));
                if (ov < sec) sec = ov;
                m1 = p;
            } else if (v < sec) sec = v;
            float w = t2b[tid * 8 + i];
            if (w < sec) sec = w;
        }
        best1[tid] = m1;
        idxs[tid]  = (int)(m1 & 0xffffffffull);
        bestB[tid] = ~0ull;
        float bv = __uint_as_float((unsigned)(m1 >> 32));
        if (sec - bv <= MARGIN) {
            int slot = atomicAdd(nflagp, 1);
            frows[slot] = tid;
        }
    }
    __syncthreads();
    int nf = nflagp[0];

    // ================= pass B: exact rescore of flagged rows ==============
    if (nf > 0) {
        for (int chunk = 0; chunk < NCHUNK; chunk++) {
            __syncthreads();
            const float* eblk = emb + (size_t)chunk * TC * DIMS;
            for (int i = tid; i < TC * (DIMS / 4); i += 256) {
                int c  = i >> 6;
                int k4 = i & 63;
                float4 v = ((const float4*)eblk)[(size_t)c * (DIMS / 4) + k4];
                *(float4*)&es2[c * RSTR2 + 4 * k4] = v;
            }
            __syncthreads();
            int c = tid & 63;
            int q = tid >> 6;
            for (int f = 0; f < nf; f++) {
                int fr = frows[f];
                const float4* zr =
                    (const float4*)(z + ((size_t)(rowBase + fr)) * DIMS + q * 64);
                const float4* er = (const float4*)&es2[c * RSTR2 + q * 64];
                float d0 = 0.f, d1 = 0.f, d2 = 0.f, d3 = 0.f;
#pragma unroll 4
                for (int k4 = 0; k4 < 16; k4++) {
                    float4 zv = __ldg(&zr[k4]);
                    float4 ev = er[k4];
                    d0 = fmaf(zv.x, ev.x, d0);
                    d1 = fmaf(zv.y, ev.y, d1);
                    d2 = fmaf(zv.z, ev.z, d2);
                    d3 = fmaf(zv.w, ev.w, d3);
                }
                pbuf[c * 4 + q] = __fadd_rn(__fadd_rn(d0, d1), __fadd_rn(d2, d3));
                __syncthreads();
                if (tid < 64) {
                    float dot = __fadd_rn(__fadd_rn(pbuf[tid * 4 + 0], pbuf[tid * 4 + 1]),
                                          __fadd_rn(pbuf[tid * 4 + 2], pbuf[tid * 4 + 3]));
                    int code   = chunk * TC + tid;
                    float t    = __fadd_rn(z2s[fr], g_e2[code]);
                    float dist = __fsub_rn(t, __fmul_rn(2.0f, dot));
                    unsigned long long p =
                        ((unsigned long long)FU(dist) << 32) | (unsigned)code;
                    atomicMin(&bestB[fr], p);
                }
                __syncthreads();
            }
        }
        __syncthreads();
        if (tid < nf) {
            int fr = frows[tid];
            idxs[fr] = (int)(bestB[fr] & 0xffffffffull);
        }
    }
    __syncthreads();

    // ================= epilogue: gather / STE / loss ======================
    double lsum = 0.0;
    float* outblk = out + (size_t)rowBase * DIMS;
    for (int i = tid; i < TM * (DIMS / 4); i += 256) {
        int r  = i >> 6;
        int k4 = i & 63;
        float4 zv = __ldg(&((const float4*)zblk)[(size_t)r * (DIMS / 4) + k4]);
        float4 qv = __ldg(&((const float4*)(emb + (size_t)idxs[r] * DIMS))[k4]);
        float4 ov; float d;
        d = __fsub_rn(qv.x, zv.x); ov.x = __fadd_rn(zv.x, d); lsum += (double)__fmul_rn(d, d);
        d = __fsub_rn(qv.y, zv.y); ov.y = __fadd_rn(zv.y, d); lsum += (double)__fmul_rn(d, d);
        d = __fsub_rn(qv.z, zv.z); ov.z = __fadd_rn(zv.z, d); lsum += (double)__fmul_rn(d, d);
        d = __fsub_rn(qv.w, zv.w); ov.w = __fadd_rn(zv.w, d); lsum += (double)__fmul_rn(d, d);
        ((float4*)outblk)[i] = ov;
    }
    red[tid] = lsum;
    __syncthreads();
    for (int s = 128; s > 0; s >>= 1) {
        if (tid < s) red[tid] += red[tid + s];
        __syncthreads();
    }
    if (tid == 0) atomicAdd(&g_loss_accum, red[0]);
}

// ---------------------------------------------------------------------------
__global__ void vq_finalize(float* __restrict__ out, int out_size) {
    double mean = g_loss_accum / (double)((size_t)NROWS * DIMS);
    float loss = (float)(0.5 * mean);
    out[out_size - 2] = loss;   // commitment_loss
    out[out_size - 1] = loss;   // emb_loss
}

// ---------------------------------------------------------------------------
extern "C" void kernel_launch(void* const* d_in, const int* in_sizes, int n_in,
                              void* d_out, int out_size) {
    const float* z   = (const float*)d_in[0];
    const float* emb = (const float*)d_in[1];
    if (n_in >= 2 && in_sizes[0] == NCODES * DIMS && in_sizes[1] == NROWS * DIMS) {
        emb = (const float*)d_in[0];
        z   = (const float*)d_in[1];
    }
    float* out = (float*)d_out;

    vq_prep<<<(NCODES * 32 + 255) / 256, 256>>>(emb);

    cudaFuncSetAttribute(vq_main, cudaFuncAttributeMaxDynamicSharedMemorySize,
                         SMEM_BYTES);
    vq_main<<<NROWS / TM, 256, SMEM_BYTES>>>(z, emb, out);

    vq_finalize<<<1, 1>>>(out, out_size);
}